// round 10
// baseline (speedup 1.0000x reference)
#include <cuda_runtime.h>
#include <cstddef>

// GroupedESNCell, round 7: numerics identical to R5/R6 (int16+int4, 4.02e-5).
// Throughput rework based on issue-bound diagnosis:
//   - packed f32x2 math kept in 64-bit registers end-to-end ("l" constraints)
//     -> eliminates per-op mov.b64 pack/unpack overhead
//   - explicit 2-stage register prefetch of weights in the k-loop
//   - per-group barrier + partial L1 residency kept from R6

#define G 8
#define H 2048
#define T_STEPS 4096
#define NCTA 128
#define CTAS_PER_GROUP (NCTA / G)             // 16
#define ROWS_PER_CTA (H / CTAS_PER_GROUP)     // 128
#define THREADS 512
#define NWARPS (THREADS / 32)                 // 16
#define ROWS_PER_WARP (ROWS_PER_CTA / NWARPS) // 8
#define RADIUS_F 100.0f
#define LEAKY_F 1.0f
#define NROWS_TOTAL (G * H)                   // 16384
#define NGRP 256                              // column groups per row (8 cols each)
#define L1_WARPS 4

typedef unsigned long long u64;
// bits of (-(2^23+32768), -(2^23+32768)) as packed f32x2
#define NEGM2 0xCB008000CB008000ULL

// ---- global scratch (allocation-free) ----
__device__ unsigned int g_wq[(size_t)G * H * H / 2];   // 67 MB q16 (split layout)
__device__ unsigned int g_wr[(size_t)G * H * H / 8];   // 16.8 MB q4 residual
__device__ float g_step[NROWS_TOTAL];
__device__ float g_pre[2][G * H];
__device__ float g_psq[2][NCTA];
__device__ unsigned int g_cnt[G * 32];
__device__ unsigned int g_epoch[G * 32];

// ============================================================================
// Prep kernel A: per-row max|w| -> step = rowmax/32767 (one warp per row)
// ============================================================================
__global__ void rowscale_kernel(const float* __restrict__ W_hh)
{
    const int warp = threadIdx.x >> 5;
    const int lane = threadIdx.x & 31;
    const int row  = blockIdx.x * 8 + warp;
    const float* w = W_hh + (size_t)row * H;

    float m = 0.0f;
    #pragma unroll
    for (int k = 0; k < H / 32; ++k)
        m = fmaxf(m, fabsf(w[lane + 32 * k]));
    #pragma unroll
    for (int s = 16; s > 0; s >>= 1)
        m = fmaxf(m, __shfl_xor_sync(0xffffffffu, m, s));
    if (lane == 0)
        g_step[row] = fmaxf(m, 1e-30f) * (1.0f / 32767.0f);
}

// ============================================================================
// Prep kernel B: quantize. One thread per (row, group): 8 elements
// (cols {4i..4i+3, 4i+1024..4i+1027}) -> uint4 biased-u16 + u32 of 8 nibbles
// ============================================================================
__global__ void quantize_kernel(const float* __restrict__ W_hh)
{
    const int gid = blockIdx.x * blockDim.x + threadIdx.x;
    if (gid >= NROWS_TOTAL * NGRP) return;
    const int row = gid >> 8;
    const int i   = gid & (NGRP - 1);
    const float* wr = W_hh + (size_t)row * H;
    const float inv = 1.0f / g_step[row];

    float4 wa = *(const float4*)(wr + 4 * i);
    float4 wb = *(const float4*)(wr + 4 * i + 1024);
    float v[8] = {wa.x, wa.y, wa.z, wa.w, wb.x, wb.y, wb.z, wb.w};

    unsigned int u16v[8];
    unsigned int nib = 0;
    #pragma unroll
    for (int j = 0; j < 8; ++j) {
        float s = v[j] * inv;
        int q = __float2int_rn(s);
        q = min(max(q, -32767), 32767);
        float r = s - (float)q;
        int q4 = __float2int_rn(r * 16.0f);
        q4 = min(max(q4, -8), 7);
        u16v[j] = (unsigned int)(q + 32768);
        nib |= (unsigned int)(q4 & 0xF) << (4 * j);
    }
    uint4 qs;
    qs.x = u16v[0] | (u16v[1] << 16);
    qs.y = u16v[2] | (u16v[3] << 16);
    qs.z = u16v[4] | (u16v[5] << 16);
    qs.w = u16v[6] | (u16v[7] << 16);
    ((uint4*)g_wq)[(size_t)row * NGRP + i] = qs;
    g_wr[(size_t)row * NGRP + i] = nib;
}

// ============================================================================
// packed f32x2 helpers, 64-bit registers end-to-end
// ============================================================================
// dequant packed pair of biased u16 -> f32x2 pair of centered q16 values
__device__ __forceinline__ u64 dq2(unsigned int p, u64 negm)
{
    u64 r;
    asm("{\n\t.reg .b32 lo, hi;\n\t"
        "prmt.b32 lo, %1, %2, 0x7610;\n\t"
        "prmt.b32 hi, %1, %2, 0x7632;\n\t"
        "mov.b64 %0, {lo, hi};\n\t"
        "add.rn.f32x2 %0, %0, %3;\n\t}"
        : "=l"(r) : "r"(p), "r"(0x4B000000u), "l"(negm));
    return r;
}
__device__ __forceinline__ u64 fma2(u64 a, u64 b, u64 c)
{
    u64 d;
    asm("fma.rn.f32x2 %0, %1, %2, %3;" : "=l"(d) : "l"(a), "l"(b), "l"(c));
    return d;
}
__device__ __forceinline__ float unpack_sum(u64 a)
{
    float lo, hi;
    asm("mov.b64 {%0, %1}, %2;" : "=f"(lo), "=f"(hi) : "l"(a));
    return lo + hi;
}
__device__ __forceinline__ unsigned int pack4(int a, int b, int c, int d)
{
    return (a & 0xFF) | ((b & 0xFF) << 8) | ((c & 0xFF) << 16) | ((d & 0xFF) << 24);
}
__device__ __forceinline__ void acc_res(int& dp, unsigned int x, uint2 hp)
{
    int e = (int)((x << 4) & 0xF0F0F0F0u);   // even cols: 16*q4 as s8
    int o = (int)(x & 0xF0F0F0F0u);
    dp = __dp4a(e, (int)hp.x, dp);
    dp = __dp4a(o, (int)hp.y, dp);
}

// 4-row block with explicit 2-stage register prefetch.
template <bool USE_L1>
__device__ __forceinline__ void do_block4(
    const uint4* __restrict__ wqb, const unsigned int* __restrict__ wrb,
    const ulonglong2* __restrict__ hs2, const uint2* __restrict__ hs8,
    int lane, float hstep256,
    float& v0, float& v1, float& v2, float& v3)
{
    const u64 negm = NEGM2;
    u64 a0 = 0ULL, a1 = 0ULL, a2 = 0ULL, a3 = 0ULL;   // (0.0f,0.0f)
    int dp0 = 0, dp1 = 0, dp2 = 0, dp3 = 0;

    uint4 qa[2], qb[2], qc[2], qd[2];
    unsigned int xa[2], xb[2], xc[2], xd[2];

#define LDW(slot, idx)                                              \
    do {                                                            \
        if (USE_L1) {                                               \
            qa[slot] = __ldca(&wqb[(idx)]);                         \
            qb[slot] = __ldca(&wqb[(idx) + NGRP]);                  \
            qc[slot] = __ldca(&wqb[(idx) + 2 * NGRP]);              \
            qd[slot] = __ldca(&wqb[(idx) + 3 * NGRP]);              \
            xa[slot] = __ldca(&wrb[(idx)]);                         \
            xb[slot] = __ldca(&wrb[(idx) + NGRP]);                  \
            xc[slot] = __ldca(&wrb[(idx) + 2 * NGRP]);              \
            xd[slot] = __ldca(&wrb[(idx) + 3 * NGRP]);              \
        } else {                                                    \
            qa[slot] = __ldcg(&wqb[(idx)]);                         \
            qb[slot] = __ldcg(&wqb[(idx) + NGRP]);                  \
            qc[slot] = __ldcg(&wqb[(idx) + 2 * NGRP]);              \
            qd[slot] = __ldcg(&wqb[(idx) + 3 * NGRP]);              \
            xa[slot] = __ldcg(&wrb[(idx)]);                         \
            xb[slot] = __ldcg(&wrb[(idx) + NGRP]);                  \
            xc[slot] = __ldcg(&wrb[(idx) + 2 * NGRP]);              \
            xd[slot] = __ldcg(&wrb[(idx) + 3 * NGRP]);              \
        }                                                           \
    } while (0)

    LDW(0, lane);                                   // prime k=0
    #pragma unroll
    for (int k = 0; k < 8; ++k) {
        const int cur = k & 1;
        if (k < 7) LDW(cur ^ 1, lane + 32 * (k + 1));   // prefetch k+1

        const int i = lane + 32 * k;
        ulonglong2 ha = hs2[i];          // cols 4i..4i+3 as 2 f32x2 pairs
        ulonglong2 hb = hs2[i + 256];    // cols 4i+1024..4i+1027
        uint2 hp = hs8[i];

        a0 = fma2(dq2(qa[cur].x, negm), ha.x, a0);
        a0 = fma2(dq2(qa[cur].y, negm), ha.y, a0);
        a0 = fma2(dq2(qa[cur].z, negm), hb.x, a0);
        a0 = fma2(dq2(qa[cur].w, negm), hb.y, a0);
        a1 = fma2(dq2(qb[cur].x, negm), ha.x, a1);
        a1 = fma2(dq2(qb[cur].y, negm), ha.y, a1);
        a1 = fma2(dq2(qb[cur].z, negm), hb.x, a1);
        a1 = fma2(dq2(qb[cur].w, negm), hb.y, a1);
        a2 = fma2(dq2(qc[cur].x, negm), ha.x, a2);
        a2 = fma2(dq2(qc[cur].y, negm), ha.y, a2);
        a2 = fma2(dq2(qc[cur].z, negm), hb.x, a2);
        a2 = fma2(dq2(qc[cur].w, negm), hb.y, a2);
        a3 = fma2(dq2(qd[cur].x, negm), ha.x, a3);
        a3 = fma2(dq2(qd[cur].y, negm), ha.y, a3);
        a3 = fma2(dq2(qd[cur].z, negm), hb.x, a3);
        a3 = fma2(dq2(qd[cur].w, negm), hb.y, a3);

        acc_res(dp0, xa[cur], hp);
        acc_res(dp1, xb[cur], hp);
        acc_res(dp2, xc[cur], hp);
        acc_res(dp3, xd[cur], hp);
    }
#undef LDW

    v0 = fmaf(hstep256, (float)dp0, unpack_sum(a0));
    v1 = fmaf(hstep256, (float)dp1, unpack_sum(a1));
    v2 = fmaf(hstep256, (float)dp2, unpack_sum(a2));
    v3 = fmaf(hstep256, (float)dp3, unpack_sum(a3));
}

// ============================================================================
// Persistent recurrence kernel
// ============================================================================
__global__ __launch_bounds__(THREADS, 1)
void esn_persistent_kernel(const float* __restrict__ x,
                           const float* __restrict__ W_ih,
                           float* __restrict__ out)
{
    __shared__ __align__(16) float h_sh[H];
    __shared__ __align__(8) uint2 hs8_sh[NGRP];
    __shared__ float x_sh[T_STEPS];
    __shared__ float wih_sh[ROWS_PER_CTA];
    __shared__ float step_sh[ROWS_PER_CTA];
    __shared__ float red_sh[NWARPS];
    __shared__ float coef_sh;
    __shared__ float hstep256_sh;
    __shared__ float invh_sh;

    const int tid  = threadIdx.x;
    const int cta  = blockIdx.x;
    const int g    = cta / CTAS_PER_GROUP;
    const int sub  = cta % CTAS_PER_GROUP;
    const int rowbase = sub * ROWS_PER_CTA;
    const int warp = tid >> 5;
    const int lane = tid & 31;

    const float lr   = (LEAKY_F * (float)(G - g)) / (float)G;
    const float leak = 1.0f - lr;

    const uint4* Wq = (const uint4*)g_wq + (size_t)g * H * NGRP;
    const unsigned int* Wr = g_wr + (size_t)g * H * NGRP;
    const ulonglong2* hs2 = (const ulonglong2*)h_sh;
    const float4* hs4 = (const float4*)h_sh;

    for (int i = tid; i < H; i += THREADS) h_sh[i] = 0.0f;
    for (int i = tid; i < NGRP; i += THREADS) hs8_sh[i] = make_uint2(0u, 0u);
    for (int i = tid; i < T_STEPS; i += THREADS) x_sh[i] = x[i];
    if (tid < ROWS_PER_CTA) {
        wih_sh[tid]  = W_ih[rowbase + tid];
        step_sh[tid] = g_step[g * H + rowbase + tid];
    }
    if (tid == 0) { hstep256_sh = 0.0f; invh_sh = 0.0f; }
    __syncthreads();

    unsigned int* const cntp = &g_cnt[g * 32];
    volatile unsigned int* const epop = (volatile unsigned int*)&g_epoch[g * 32];

    for (int t = 0; t < T_STEPS; ++t) {
        const int par = t & 1;
        const float xt = x_sh[t];
        const float hstep256 = hstep256_sh;

        // ============ Phase A: quantized matvec, 8 rows per warp ============
        float warp_sq = 0.0f;
        const int wrow0 = rowbase + warp * ROWS_PER_WARP;

        #pragma unroll 1
        for (int rr = 0; rr < ROWS_PER_WARP; rr += 4) {
            const int r0 = wrow0 + rr;
            const uint4* wqb = Wq + (size_t)r0 * NGRP;
            const unsigned int* wrb = Wr + (size_t)r0 * NGRP;

            float v0, v1, v2, v3;
            if (warp < L1_WARPS)
                do_block4<true >(wqb, wrb, hs2, hs8_sh, lane, hstep256,
                                 v0, v1, v2, v3);
            else
                do_block4<false>(wqb, wrb, hs2, hs8_sh, lane, hstep256,
                                 v0, v1, v2, v3);

            #pragma unroll
            for (int s = 16; s > 0; s >>= 1) {
                v0 += __shfl_xor_sync(0xffffffffu, v0, s);
                v1 += __shfl_xor_sync(0xffffffffu, v1, s);
                v2 += __shfl_xor_sync(0xffffffffu, v2, s);
                v3 += __shfl_xor_sync(0xffffffffu, v3, s);
            }
            if (lane == 0) {
                const int lr0 = r0 - rowbase;
                const float p0 = fmaf(step_sh[lr0],     v0, xt * wih_sh[lr0]);
                const float p1 = fmaf(step_sh[lr0 + 1], v1, xt * wih_sh[lr0 + 1]);
                const float p2 = fmaf(step_sh[lr0 + 2], v2, xt * wih_sh[lr0 + 2]);
                const float p3 = fmaf(step_sh[lr0 + 3], v3, xt * wih_sh[lr0 + 3]);
                __stcg((float4*)&g_pre[par][g * H + r0],
                       make_float4(p0, p1, p2, p3));
                warp_sq += p0 * p0 + p1 * p1 + p2 * p2 + p3 * p3;
            }
        }
        if (lane == 0) red_sh[warp] = warp_sq;
        __syncthreads();
        if (tid == 0) {
            float s = 0.0f;
            #pragma unroll
            for (int w = 0; w < NWARPS; ++w) s += red_sh[w];
            __stcg(&g_psq[par][cta], s);
        }

        // ============ per-GROUP barrier (16 CTAs) ============
        __threadfence();
        if (tid == 0) {
            const unsigned int snap = *epop;
            const unsigned int old = atomicAdd(cntp, 1u);
            if (old == CTAS_PER_GROUP - 1u) {
                *cntp = 0u;
                __threadfence();
                atomicAdd((unsigned int*)epop, 1u);
            } else {
                while (*epop == snap) { }
            }
        }
        __syncthreads();
        __threadfence();

        // ============ Phase B: norm + state update + h8 repack ==============
        if (tid == 0) {
            float s = 0.0f;
            #pragma unroll
            for (int c = 0; c < CTAS_PER_GROUP; ++c)
                s += __ldcg(&g_psq[par][g * CTAS_PER_GROUP + c]);
            coef_sh = lr * RADIUS_F * rsqrtf(s);
        }
        __syncthreads();
        const float cb = coef_sh;
        const float4* preg = (const float4*)&g_pre[par][g * H];
        float4* hmut = (float4*)h_sh;
        float m = 0.0f;
        {
            const int idx = tid;                 // 512 threads x float4 = H
            float4 p  = __ldcg(&preg[idx]);
            float4 hv = hmut[idx];
            hv.x = leak * hv.x + cb * p.x;
            hv.y = leak * hv.y + cb * p.y;
            hv.z = leak * hv.z + cb * p.z;
            hv.w = leak * hv.w + cb * p.w;
            hmut[idx] = hv;
            m = fmaxf(fmaxf(fabsf(hv.x), fabsf(hv.y)),
                      fmaxf(fabsf(hv.z), fabsf(hv.w)));
        }
        #pragma unroll
        for (int s = 16; s > 0; s >>= 1)
            m = fmaxf(m, __shfl_xor_sync(0xffffffffu, m, s));
        if (lane == 0) red_sh[warp] = m;
        __syncthreads();
        if (tid == 0) {
            float mm = 0.0f;
            #pragma unroll
            for (int w = 0; w < NWARPS; ++w) mm = fmaxf(mm, red_sh[w]);
            const float hstep = mm * (1.0f / 127.0f);
            hstep256_sh = hstep * (1.0f / 256.0f);
            invh_sh = (mm > 0.0f) ? 127.0f / mm : 0.0f;
        }
        __syncthreads();
        if (tid < NGRP) {
            const float inv = invh_sh;
            float4 ha = hs4[tid];
            float4 hb = hs4[tid + 256];
            int q0 = __float2int_rn(ha.x * inv);
            int q1 = __float2int_rn(ha.y * inv);
            int q2 = __float2int_rn(ha.z * inv);
            int q3 = __float2int_rn(ha.w * inv);
            int q4 = __float2int_rn(hb.x * inv);
            int q5 = __float2int_rn(hb.y * inv);
            int q6 = __float2int_rn(hb.z * inv);
            int q7 = __float2int_rn(hb.w * inv);
            hs8_sh[tid] = make_uint2(pack4(q0, q2, q4, q6),
                                     pack4(q1, q3, q5, q7));
        }
        if (tid < ROWS_PER_CTA) {
            __stcs(&out[(size_t)t * (G * H) + (size_t)g * H + rowbase + tid],
                   h_sh[rowbase + tid]);
        }
        __syncthreads();
    }
}

extern "C" void kernel_launch(void* const* d_in, const int* in_sizes, int n_in,
                              void* d_out, int out_size)
{
    const float* x    = (const float*)d_in[0];   // [T, 1]
    const float* W_ih = (const float*)d_in[1];   // [H, 1]
    const float* W_hh = (const float*)d_in[2];   // [G, H, H]
    float* out = (float*)d_out;                  // [T, G*H]

    rowscale_kernel<<<NROWS_TOTAL / 8, 256>>>(W_hh);
    quantize_kernel<<<(NROWS_TOTAL * NGRP + 255) / 256, 256>>>(W_hh);
    esn_persistent_kernel<<<NCTA, THREADS>>>(x, W_ih, out);
}